// round 15
// baseline (speedup 1.0000x reference)
#include <cuda_runtime.h>
#include <cuda_bf16.h>
#include <cstdint>

#define D 64
#define MAXN 100000

// Scratch accumulator g[N, 64] (static __device__: no allocs allowed)
__device__ __align__(16) float g_scratch[MAXN * D];

// ---------------------------------------------------------------------------
// Scatter:  g[dst[e], :] += (ci[src[e]] * drop_mask[e]) * review_feat[e, :]
// Round-12 proven form (~29us, near LTS-capacity floor): coalesced metadata,
// ballot skips ~70% exact-zero dropout edges, 2 live edges/iter,
// LDG.128 + red.global.add.v4.f32.
// ---------------------------------------------------------------------------
__global__ void scatter_kernel(const float4* __restrict__ rf,
                               const float*  __restrict__ ci,
                               const float*  __restrict__ dm,
                               const int*    __restrict__ src,
                               const int*    __restrict__ dst,
                               int E) {
    int warp = (blockIdx.x * blockDim.x + threadIdx.x) >> 5;
    int lane = threadIdx.x & 31;
    int ebase = warp * 32;
    int e = ebase + lane;

    float m = 0.f, s = 0.f;
    int d = 0;
    if (e < E) {
        m = dm[e];
        if (m != 0.f) {
            d = dst[e];
            s = ci[src[e]] * m;
        }
    }
    unsigned mask = __ballot_sync(0xFFFFFFFFu, m != 0.f);

    int half = lane >> 4;
    int q = lane & 15;

    while (mask) {
        int l0 = __ffs(mask) - 1; mask &= mask - 1;
        int l1 = -1;
        if (mask) { l1 = __ffs(mask) - 1; mask &= mask - 1; }

        int l = half ? l1 : l0;
        int lsafe = (l >= 0) ? l : l0;
        float sv = __shfl_sync(0xFFFFFFFFu, s, lsafe);
        int   dv = __shfl_sync(0xFFFFFFFFu, d, lsafe);

        if (l >= 0) {
            float4 v = rf[(size_t)(ebase + l) * 16 + q];
            v.x *= sv; v.y *= sv; v.z *= sv; v.w *= sv;
            float* p = &g_scratch[(size_t)dv * D + q * 4];
            asm volatile("red.global.add.v4.f32 [%0], {%1, %2, %3, %4};"
                         :: "l"(p), "f"(v.x), "f"(v.y), "f"(v.z), "f"(v.w)
                         : "memory");
        }
    }
}

// ===========================================================================
// HMMA GEMM: out = (g @ W^T) * ci, fp32 via bf16 Karatsuba 3-pass split.
// OCCUPANCY-FIRST shape: warp tile 16 rows x 32 cols (acc = 16 regs),
// block = 64 rows x 64 cols (8 warps: stripe = w>>1, col-half = w&1),
// __launch_bounds__(256, 4) -> 4 blocks/SM (regs capped at 64).
// A: direct LDG.64 fragments from L2-resident g_scratch, bf16-split in regs
//    (round-14 verified layout: rows lane>>2/+8, k (lane&3)*2/+8).
// B: smem, swizzled ldmatrix.x4 (round-13 verified plan: m0/m1 = octet0
//    k-lo/hi, m2/m3 = octet1 k-lo/hi).
// ===========================================================================
__device__ __forceinline__ uint32_t smem_u32(const void* p) {
    uint32_t a;
    asm("{ .reg .u64 t; cvta.to.shared.u64 t, %1; cvt.u32.u64 %0, t; }"
        : "=r"(a) : "l"(p));
    return a;
}
__device__ __forceinline__ void ldsm_x4(uint32_t& r0, uint32_t& r1,
                                        uint32_t& r2, uint32_t& r3, uint32_t a) {
    asm volatile("ldmatrix.sync.aligned.m8n8.x4.shared.b16 {%0,%1,%2,%3}, [%4];"
                 : "=r"(r0), "=r"(r1), "=r"(r2), "=r"(r3) : "r"(a));
}
__device__ __forceinline__ void mma_bf16(float* d, const uint32_t* a,
                                         uint32_t b0, uint32_t b1) {
    asm volatile("mma.sync.aligned.m16n8k16.row.col.f32.bf16.bf16.f32 "
                 "{%0,%1,%2,%3}, {%4,%5,%6,%7}, {%8,%9}, {%0,%1,%2,%3};"
                 : "+f"(d[0]), "+f"(d[1]), "+f"(d[2]), "+f"(d[3])
                 : "r"(a[0]), "r"(a[1]), "r"(a[2]), "r"(a[3]),
                   "r"(b0), "r"(b1));
}
__device__ __forceinline__ void split2(float2 x, uint32_t& h, uint32_t& l) {
    __nv_bfloat162 h2 = __float22bfloat162_rn(x);
    float2 hf = __bfloat1622float2(h2);
    __nv_bfloat162 l2 = __float22bfloat162_rn(make_float2(x.x - hf.x, x.y - hf.y));
    h = *reinterpret_cast<uint32_t*>(&h2);
    l = *reinterpret_cast<uint32_t*>(&l2);
}
__device__ __forceinline__ void split4w(const float4& x, uint2& hv, uint2& lv) {
    split2(make_float2(x.x, x.y), hv.x, lv.x);
    split2(make_float2(x.z, x.w), hv.y, lv.y);
}

__global__ void __launch_bounds__(256, 4)
gemm_mma_kernel(const float* __restrict__ W, const float* __restrict__ ci,
                float* __restrict__ out, int N) {
    __shared__ __align__(128) char smem[16384];   // WHI [0,8K), WLO [8K,16K)
    uint32_t sb = smem_u32(smem);
    int tid = threadIdx.x, w = tid >> 5, lane = tid & 31;
    int row0 = blockIdx.x * 64;

    // ---- convert W -> bf16 hi/lo, swizzled 16B chunks (512 chunks) ----
    #pragma unroll
    for (int i = tid; i < 512; i += 256) {
        int f = i >> 3, c = i & 7;
        const float4* wp = reinterpret_cast<const float4*>(W) + f * 16 + c * 2;
        float4 x0 = wp[0], x1 = wp[1];
        uint2 h0, l0, h1, l1;
        split4w(x0, h0, l0);
        split4w(x1, h1, l1);
        uint32_t off = (uint32_t)f * 128 + (uint32_t)((c ^ (f & 7)) << 4);
        *reinterpret_cast<uint4*>(smem + off)        = make_uint4(h0.x, h0.y, h1.x, h1.y);
        *reinterpret_cast<uint4*>(smem + 8192 + off) = make_uint4(l0.x, l0.y, l1.x, l1.y);
    }
    __syncthreads();

    int stripe = w >> 1;        // rows row0 + stripe*16 .. +15
    int chalf = w & 1;          // cols chalf*32 .. +31

    // A fragment coords (verified round 14)
    int grp = lane >> 2;
    int kin = (lane & 3) * 2;
    int rA = row0 + stripe * 16 + grp;
    int rB = rA + 8;
    bool okA = rA < N, okB = rB < N;
    const float* gA = &g_scratch[(size_t)rA * D];
    const float* gB = &g_scratch[(size_t)rB * D];

    // B ldmatrix.x4 lane plan (verified round 13):
    // n = nbase + ((lane>>4)&1)*8 + (lane&7); k-half = (lane>>3)&1
    int bn_off = ((lane >> 4) & 1) * 8 + (lane & 7);
    int bkp = (lane >> 3) & 1;

    float acc[4][4];            // [nb][frag], nb = col octet within half
    #pragma unroll
    for (int nb = 0; nb < 4; nb++)
        #pragma unroll
        for (int j = 0; j < 4; j++) acc[nb][j] = 0.f;

    #pragma unroll
    for (int kc = 0; kc < 4; kc++) {
        // A: 4 LDG.64 from L2-resident g, split in regs
        int k0 = kc * 16 + kin;
        float2 z = make_float2(0.f, 0.f);
        float2 x00 = okA ? *reinterpret_cast<const float2*>(gA + k0)     : z;
        float2 x10 = okB ? *reinterpret_cast<const float2*>(gB + k0)     : z;
        float2 x01 = okA ? *reinterpret_cast<const float2*>(gA + k0 + 8) : z;
        float2 x11 = okB ? *reinterpret_cast<const float2*>(gB + k0 + 8) : z;
        uint32_t AH[4], AL[4];
        split2(x00, AH[0], AL[0]);
        split2(x10, AH[1], AL[1]);
        split2(x01, AH[2], AL[2]);
        split2(x11, AH[3], AL[3]);

        // B: 2 octet-pairs for this col-half, hi + lo (4 ldsm.x4)
        uint32_t BH[2][4], BL[2][4];
        uint32_t chunk = (uint32_t)(2 * kc + bkp);
        #pragma unroll
        for (int nbp = 0; nbp < 2; nbp++) {
            int n = chalf * 32 + nbp * 16 + bn_off;
            uint32_t boff = (uint32_t)n * 128 + ((chunk ^ (uint32_t)(n & 7)) << 4);
            ldsm_x4(BH[nbp][0], BH[nbp][1], BH[nbp][2], BH[nbp][3], sb + boff);
            ldsm_x4(BL[nbp][0], BL[nbp][1], BL[nbp][2], BL[nbp][3], sb + 8192 + boff);
        }

        #pragma unroll
        for (int nbp = 0; nbp < 2; nbp++) {
            mma_bf16(acc[2 * nbp],     AH, BH[nbp][0], BH[nbp][1]);  // hi*hi
            mma_bf16(acc[2 * nbp + 1], AH, BH[nbp][2], BH[nbp][3]);
            mma_bf16(acc[2 * nbp],     AH, BL[nbp][0], BL[nbp][1]);  // hi*lo
            mma_bf16(acc[2 * nbp + 1], AH, BL[nbp][2], BL[nbp][3]);
            mma_bf16(acc[2 * nbp],     AL, BH[nbp][0], BH[nbp][1]);  // lo*hi
            mma_bf16(acc[2 * nbp + 1], AL, BH[nbp][2], BH[nbp][3]);
        }
    }

    // ---- epilogue: scale by ci[row], float2 stores ----
    int tig = lane & 3;
    float cA = okA ? ci[rA] : 0.f;
    float cB = okB ? ci[rB] : 0.f;
    #pragma unroll
    for (int nb = 0; nb < 4; nb++) {
        int col = chalf * 32 + nb * 8 + 2 * tig;
        if (okA) {
            float2 v = make_float2(acc[nb][0] * cA, acc[nb][1] * cA);
            *reinterpret_cast<float2*>(&out[(size_t)rA * D + col]) = v;
        }
        if (okB) {
            float2 v = make_float2(acc[nb][2] * cB, acc[nb][3] * cB);
            *reinterpret_cast<float2*>(&out[(size_t)rB * D + col]) = v;
        }
    }
}

// ---------------------------------------------------------------------------
// Launch
// Inputs: review_feat [E,64] f32, ci [N,1] f32, W [64,64] f32,
//         drop_mask [E,1] f32, src [E] i32, dst [E] i32.  Output: [N,64] f32
// ---------------------------------------------------------------------------
extern "C" void kernel_launch(void* const* d_in, const int* in_sizes, int n_in,
                              void* d_out, int out_size) {
    const float4* rf  = (const float4*)d_in[0];
    const float*  ci  = (const float*) d_in[1];
    const float*  W   = (const float*) d_in[2];
    const float*  dm  = (const float*) d_in[3];
    const int*    src = (const int*)   d_in[4];
    const int*    dst = (const int*)   d_in[5];
    float* out = (float*)d_out;

    int E = in_sizes[4];
    int N = in_sizes[1];

    // 1. zero scratch accumulator (graph-capturable memset node)
    void* gptr = nullptr;
    cudaGetSymbolAddress(&gptr, g_scratch);
    cudaMemsetAsync(gptr, 0, (size_t)N * D * sizeof(float), 0);

    // 2. warp-cooperative scatter-accumulate (dropout-sparse, REDG.v4)
    int warps = (E + 31) / 32;
    int sblocks = (warps * 32 + 255) / 256;
    scatter_kernel<<<sblocks, 256>>>(rf, ci, dm, src, dst, E);

    // 3. HMMA GEMM (bf16 3-pass split, 16x32 warp tile, 4 blocks/SM)
    int gblocks = (N + 63) / 64;
    gemm_mma_kernel<<<gblocks, 256>>>(W, ci, out, N);
}

// round 16
// speedup vs baseline: 1.1715x; 1.1715x over previous
#include <cuda_runtime.h>
#include <cuda_bf16.h>
#include <cstdint>

#define D 64
#define MAXN 100000

// Scratch accumulator g[N, 64] (static __device__: no allocs allowed)
__device__ __align__(16) float g_scratch[MAXN * D];

// ---------------------------------------------------------------------------
// Scatter:  g[dst[e], :] += (ci[src[e]] * drop_mask[e]) * review_feat[e, :]
// Round-12 proven form (~29us). NEW: __ldcs streaming hints on all single-use
// streams (rf, dm, src, dst) so they evict-first in L2 and do NOT evict the
// 25.6MB g accumulator -- g stays L2-resident for the GEMM that follows.
// ---------------------------------------------------------------------------
__global__ void scatter_kernel(const float4* __restrict__ rf,
                               const float*  __restrict__ ci,
                               const float*  __restrict__ dm,
                               const int*    __restrict__ src,
                               const int*    __restrict__ dst,
                               int E) {
    int warp = (blockIdx.x * blockDim.x + threadIdx.x) >> 5;
    int lane = threadIdx.x & 31;
    int ebase = warp * 32;
    int e = ebase + lane;

    float m = 0.f, s = 0.f;
    int d = 0;
    if (e < E) {
        m = __ldcs(&dm[e]);              // streamed once
        if (m != 0.f) {
            d = __ldcs(&dst[e]);         // streamed once
            s = __ldg(&ci[__ldcs(&src[e])]) * m;   // ci reused -> keep cached
        }
    }
    unsigned mask = __ballot_sync(0xFFFFFFFFu, m != 0.f);

    int half = lane >> 4;
    int q = lane & 15;

    while (mask) {
        int l0 = __ffs(mask) - 1; mask &= mask - 1;
        int l1 = -1;
        if (mask) { l1 = __ffs(mask) - 1; mask &= mask - 1; }

        int l = half ? l1 : l0;
        int lsafe = (l >= 0) ? l : l0;
        float sv = __shfl_sync(0xFFFFFFFFu, s, lsafe);
        int   dv = __shfl_sync(0xFFFFFFFFu, d, lsafe);

        if (l >= 0) {
            float4 v = __ldcs(&rf[(size_t)(ebase + l) * 16 + q]);  // streamed once
            v.x *= sv; v.y *= sv; v.z *= sv; v.w *= sv;
            float* p = &g_scratch[(size_t)dv * D + q * 4];
            asm volatile("red.global.add.v4.f32 [%0], {%1, %2, %3, %4};"
                         :: "l"(p), "f"(v.x), "f"(v.y), "f"(v.z), "f"(v.w)
                         : "memory");
        }
    }
}

// ===========================================================================
// HMMA GEMM (round-12 proven shape, best measured 16.6us):
// out = (g @ W^T) * ci, fp32 via bf16 Karatsuba 3-pass split:
//   D = ghi@Whi^T + ghi@Wlo^T + glo@Whi^T   (dropped glo@Wlo ~2^-18)
// Block: 256 thr = 8 warps; tile 128 rows x 64 cols; warp = 16 rows x 64 cols.
// smem rows 128B, 16B-chunk XOR swizzle (c ^= row&7) -> conflict-free ldmatrix.
// g reads now hit L2 (kept resident by the scatter's streaming hints).
// ===========================================================================
#define SM_WHI 0
#define SM_WLO 8192
#define SM_AHI 16384
#define SM_ALO 32768
#define SM_TOTAL 49152

__device__ __forceinline__ uint32_t smem_u32(const void* p) {
    uint32_t a;
    asm("{ .reg .u64 t; cvta.to.shared.u64 t, %1; cvt.u32.u64 %0, t; }"
        : "=r"(a) : "l"(p));
    return a;
}
__device__ __forceinline__ void ldsm_x4(uint32_t& r0, uint32_t& r1,
                                        uint32_t& r2, uint32_t& r3, uint32_t a) {
    asm volatile("ldmatrix.sync.aligned.m8n8.x4.shared.b16 {%0,%1,%2,%3}, [%4];"
                 : "=r"(r0), "=r"(r1), "=r"(r2), "=r"(r3) : "r"(a));
}
__device__ __forceinline__ void ldsm_x2(uint32_t& r0, uint32_t& r1, uint32_t a) {
    asm volatile("ldmatrix.sync.aligned.m8n8.x2.shared.b16 {%0,%1}, [%2];"
                 : "=r"(r0), "=r"(r1) : "r"(a));
}
__device__ __forceinline__ void mma_bf16(float* d, const uint32_t* a,
                                         uint32_t b0, uint32_t b1) {
    asm volatile("mma.sync.aligned.m16n8k16.row.col.f32.bf16.bf16.f32 "
                 "{%0,%1,%2,%3}, {%4,%5,%6,%7}, {%8,%9}, {%0,%1,%2,%3};"
                 : "+f"(d[0]), "+f"(d[1]), "+f"(d[2]), "+f"(d[3])
                 : "r"(a[0]), "r"(a[1]), "r"(a[2]), "r"(a[3]),
                   "r"(b0), "r"(b1));
}
__device__ __forceinline__ void split4(const float4& x, uint2& hv, uint2& lv) {
    __nv_bfloat162 h01 = __float22bfloat162_rn(make_float2(x.x, x.y));
    __nv_bfloat162 h23 = __float22bfloat162_rn(make_float2(x.z, x.w));
    float2 f01 = __bfloat1622float2(h01);
    float2 f23 = __bfloat1622float2(h23);
    __nv_bfloat162 l01 = __float22bfloat162_rn(make_float2(x.x - f01.x, x.y - f01.y));
    __nv_bfloat162 l23 = __float22bfloat162_rn(make_float2(x.z - f23.x, x.w - f23.y));
    hv.x = *reinterpret_cast<uint32_t*>(&h01);
    hv.y = *reinterpret_cast<uint32_t*>(&h23);
    lv.x = *reinterpret_cast<uint32_t*>(&l01);
    lv.y = *reinterpret_cast<uint32_t*>(&l23);
}

__global__ void __launch_bounds__(256)
gemm_mma_kernel(const float* __restrict__ W, const float* __restrict__ ci,
                float* __restrict__ out, int N) {
    extern __shared__ __align__(1024) char smem[];
    uint32_t sb = smem_u32(smem);
    int tid = threadIdx.x, w = tid >> 5, lane = tid & 31;
    int row0 = blockIdx.x * 128;

    // ---- convert W -> bf16 hi/lo, swizzled 16B chunks (512 chunks) ----
    #pragma unroll
    for (int i = tid; i < 512; i += 256) {
        int f = i >> 3, c = i & 7;
        const float4* wp = reinterpret_cast<const float4*>(W) + f * 16 + c * 2;
        float4 x0 = wp[0], x1 = wp[1];
        uint2 h0, l0, h1, l1;
        split4(x0, h0, l0);
        split4(x1, h1, l1);
        uint32_t off = (uint32_t)f * 128 + (uint32_t)((c ^ (f & 7)) << 4);
        *reinterpret_cast<uint4*>(smem + SM_WHI + off) = make_uint4(h0.x, h0.y, h1.x, h1.y);
        *reinterpret_cast<uint4*>(smem + SM_WLO + off) = make_uint4(l0.x, l0.y, l1.x, l1.y);
    }
    // ---- convert g tile [128][64] -> bf16 hi/lo, swizzled (1024 chunks) ----
    #pragma unroll
    for (int i = tid; i < 1024; i += 256) {
        int r = i >> 3, c = i & 7;
        int row = row0 + r;
        float4 x0, x1;
        if (row < N) {
            const float4* gp = reinterpret_cast<const float4*>(g_scratch)
                             + (size_t)row * 16 + c * 2;
            x0 = gp[0]; x1 = gp[1];
        } else {
            x0 = make_float4(0.f, 0.f, 0.f, 0.f);
            x1 = x0;
        }
        uint2 h0, l0, h1, l1;
        split4(x0, h0, l0);
        split4(x1, h1, l1);
        uint32_t off = (uint32_t)r * 128 + (uint32_t)((c ^ (r & 7)) << 4);
        *reinterpret_cast<uint4*>(smem + SM_AHI + off) = make_uint4(h0.x, h0.y, h1.x, h1.y);
        *reinterpret_cast<uint4*>(smem + SM_ALO + off) = make_uint4(l0.x, l0.y, l1.x, l1.y);
    }
    __syncthreads();

    // ---- A fragments for this warp's 16-row stripe (cached in regs) ----
    int i8 = lane & 7;
    int halfrow = (lane >> 3) & 1;
    int kpart = lane >> 4;
    int arow = w * 16 + halfrow * 8 + i8;
    uint32_t arow_off = (uint32_t)arow * 128;
    uint32_t ar7 = (uint32_t)(arow & 7);

    uint32_t ahi[4][4], alo[4][4];
    #pragma unroll
    for (int kc = 0; kc < 4; kc++) {
        uint32_t chunk = (uint32_t)(2 * kc + kpart);
        uint32_t aoff = arow_off + ((chunk ^ ar7) << 4);
        ldsm_x4(ahi[kc][0], ahi[kc][1], ahi[kc][2], ahi[kc][3], sb + SM_AHI + aoff);
        ldsm_x4(alo[kc][0], alo[kc][1], alo[kc][2], alo[kc][3], sb + SM_ALO + aoff);
    }

    // ---- B lane plan (x2): lanes 0-7 rows n0..n0+7 (k lo), 8-15 k hi ----
    int bl = lane & 15;
    int bi = bl & 7;
    int bkp = bl >> 3;

    float acc[8][4];
    #pragma unroll
    for (int nb = 0; nb < 8; nb++)
        #pragma unroll
        for (int j = 0; j < 4; j++) acc[nb][j] = 0.f;

    #pragma unroll
    for (int nb = 0; nb < 8; nb++) {
        int n = nb * 8 + bi;
        uint32_t n_off = (uint32_t)n * 128;
        uint32_t n7 = (uint32_t)(n & 7);
        #pragma unroll
        for (int kc = 0; kc < 4; kc++) {
            uint32_t chunk = (uint32_t)(2 * kc + bkp);
            uint32_t boff = n_off + ((chunk ^ n7) << 4);
            uint32_t bh0, bh1, bl0, bl1;
            ldsm_x2(bh0, bh1, sb + SM_WHI + boff);
            ldsm_x2(bl0, bl1, sb + SM_WLO + boff);
            mma_bf16(acc[nb], ahi[kc], bh0, bh1);   // hi*hi
            mma_bf16(acc[nb], ahi[kc], bl0, bl1);   // hi*lo
            mma_bf16(acc[nb], alo[kc], bh0, bh1);   // lo*hi
        }
    }

    // ---- epilogue: scale by ci[row], float2 stores ----
    int group = lane >> 2, tig = lane & 3;
    int rA = row0 + w * 16 + group;
    int rB = rA + 8;
    float cA = (rA < N) ? ci[rA] : 0.f;
    float cB = (rB < N) ? ci[rB] : 0.f;
    #pragma unroll
    for (int nb = 0; nb < 8; nb++) {
        int col = nb * 8 + 2 * tig;
        if (rA < N) {
            float2 v = make_float2(acc[nb][0] * cA, acc[nb][1] * cA);
            *reinterpret_cast<float2*>(&out[(size_t)rA * D + col]) = v;
        }
        if (rB < N) {
            float2 v = make_float2(acc[nb][2] * cB, acc[nb][3] * cB);
            *reinterpret_cast<float2*>(&out[(size_t)rB * D + col]) = v;
        }
    }
}

// ---------------------------------------------------------------------------
// Launch
// Inputs: review_feat [E,64] f32, ci [N,1] f32, W [64,64] f32,
//         drop_mask [E,1] f32, src [E] i32, dst [E] i32.  Output: [N,64] f32
// ---------------------------------------------------------------------------
extern "C" void kernel_launch(void* const* d_in, const int* in_sizes, int n_in,
                              void* d_out, int out_size) {
    const float4* rf  = (const float4*)d_in[0];
    const float*  ci  = (const float*) d_in[1];
    const float*  W   = (const float*) d_in[2];
    const float*  dm  = (const float*) d_in[3];
    const int*    src = (const int*)   d_in[4];
    const int*    dst = (const int*)   d_in[5];
    float* out = (float*)d_out;

    int E = in_sizes[4];
    int N = in_sizes[1];

    // 1. zero scratch accumulator (graph-capturable memset node)
    void* gptr = nullptr;
    cudaGetSymbolAddress(&gptr, g_scratch);
    cudaMemsetAsync(gptr, 0, (size_t)N * D * sizeof(float), 0);

    // 2. warp-cooperative scatter (streaming hints keep g L2-resident)
    int warps = (E + 31) / 32;
    int sblocks = (warps * 32 + 255) / 256;
    scatter_kernel<<<sblocks, 256>>>(rf, ci, dm, src, dst, E);

    // 3. HMMA GEMM (bf16 3-pass split, round-12 shape) + ci scale
    int gblocks = (N + 127) / 128;
    cudaFuncSetAttribute(gemm_mma_kernel,
                         cudaFuncAttributeMaxDynamicSharedMemorySize, SM_TOTAL);
    gemm_mma_kernel<<<gblocks, 256, SM_TOTAL>>>(W, ci, out, N);
}